// round 2
// baseline (speedup 1.0000x reference)
#include <cuda_runtime.h>
#include <cstdint>

// Problem constants: B=4, S=4096, H=16, Dk=Dv=64
#define H_     16
#define DK_    64
#define DV_    64
#define HD_    1024           // floats per (b,s) row in keys/values = H*64
#define NROWS_ 16384          // B*S
#define RT_    32             // rows per smem tile
#define TPB_   8              // tiles per block -> 256 rows per block
#define NCHUNK_ 64            // row-chunks per head
#define PAD64_ 17             // b64 words per column (16 + 1 pad)
#define DECAY_ 0.95f

// Partial-sum scratch: one 64x64 tile per block (deterministic, no atomics).
__device__ float g_l1w_scratch[NCHUNK_ * H_ * DK_ * DV_];

__device__ __forceinline__ unsigned long long pack_f2(float lo, float hi) {
    unsigned long long r;
    asm("mov.b64 %0, {%1, %2};" : "=l"(r) : "f"(lo), "f"(hi));
    return r;
}
__device__ __forceinline__ void unpack_f2(unsigned long long v, float& lo, float& hi) {
    asm("mov.b64 {%0, %1}, %2;" : "=f"(lo), "=f"(hi) : "l"(v));
}
__device__ __forceinline__ void ffma2(unsigned long long& d,
                                      unsigned long long a,
                                      unsigned long long b) {
    asm("fma.rn.f32x2 %0, %1, %2, %0;" : "+l"(d) : "l"(a), "l"(b));
}

__global__ __launch_bounds__(256, 3)
void l1w_partial_kernel(const float* __restrict__ keys,
                        const float* __restrict__ values,
                        const float* __restrict__ ws) {
    // Transposed, row-pair-packed tiles: sK[col][pair] = pack(k[2p][col], k[2p+1][col])
    __shared__ unsigned long long sK[DK_ * PAD64_];
    __shared__ unsigned long long sV[DV_ * PAD64_];

    const int h   = blockIdx.x & (H_ - 1);
    const int c   = blockIdx.x >> 4;
    const int tid = threadIdx.x;

    // Compute mapping: 16x16 thread grid; thread owns cols {ti+16i} x {tj+16j}
    const int ti = tid >> 4;
    const int tj = tid & 15;
    // Fill mapping: thread stages row-pair p, float4-column c4
    const int p  = tid >> 4;          // 0..15 (rows 2p, 2p+1)
    const int c4 = tid & 15;          // float4 col (cols 4c4..4c4+3)
    const int sw_s = c4 >> 2;         // store-side swizzle key = col>>4

    const int n0 = c * (RT_ * TPB_);

    const float* kbase = keys   + (size_t)h * DK_;
    const float* vbase = values + (size_t)h * DV_;

    unsigned long long acc[4][4];
#pragma unroll
    for (int i = 0; i < 4; ++i)
#pragma unroll
        for (int j = 0; j < 4; ++j) acc[i][j] = 0ull;

    float4 kA, kB, vA, vB;
    float  w0, w1;

    // ---- prefetch tile 0 ----
    {
        const int r0 = n0 + 2 * p;
        const float* kp0 = kbase + (size_t)r0 * HD_ + c4 * 4;
        const float* vp0 = vbase + (size_t)r0 * HD_ + c4 * 4;
        kA = *(const float4*)(kp0);
        kB = *(const float4*)(kp0 + HD_);
        vA = *(const float4*)(vp0);
        vB = *(const float4*)(vp0 + HD_);
        w0 = ws[r0];
        w1 = ws[r0 + 1];
    }

    for (int t = 0; t < TPB_; ++t) {
        __syncthreads();   // previous tile's compute finished
        // ---- store staged tile into transposed packed smem (weight folded into V) ----
        {
            const float* ka = &kA.x; const float* kb = &kB.x;
            const float* va = &vA.x; const float* vb = &vB.x;
#pragma unroll
            for (int jj = 0; jj < 4; ++jj) {
                const int col = 4 * c4 + jj;
                sK[col * PAD64_ + (p ^ sw_s)] = pack_f2(ka[jj], kb[jj]);
                sV[col * PAD64_ + (p ^ sw_s)] = pack_f2(va[jj] * w0, vb[jj] * w1);
            }
        }
        __syncthreads();

        // ---- issue next tile's global loads (latency hidden under compute) ----
        if (t + 1 < TPB_) {
            const int r0 = n0 + (t + 1) * RT_ + 2 * p;
            const float* kp0 = kbase + (size_t)r0 * HD_ + c4 * 4;
            const float* vp0 = vbase + (size_t)r0 * HD_ + c4 * 4;
            kA = *(const float4*)(kp0);
            kB = *(const float4*)(kp0 + HD_);
            vA = *(const float4*)(vp0);
            vB = *(const float4*)(vp0 + HD_);
            w0 = ws[r0];
            w1 = ws[r0 + 1];
        }

        // ---- compute: 16 row-pair steps, f32x2 packed FMAs ----
#pragma unroll 4
        for (int q = 0; q < 16; ++q) {
            unsigned long long kk[4], vv[4];
#pragma unroll
            for (int i = 0; i < 4; ++i)
                kk[i] = sK[(ti + 16 * i) * PAD64_ + (q ^ i)];
#pragma unroll
            for (int j = 0; j < 4; ++j)
                vv[j] = sV[(tj + 16 * j) * PAD64_ + (q ^ j)];
#pragma unroll
            for (int i = 0; i < 4; ++i)
#pragma unroll
                for (int j = 0; j < 4; ++j)
                    ffma2(acc[i][j], kk[i], vv[j]);
        }
    }

    // ---- epilogue: lo+hi combine, write partial tile ----
    float* outp = g_l1w_scratch + ((size_t)blockIdx.x << 12);
#pragma unroll
    for (int i = 0; i < 4; ++i)
#pragma unroll
        for (int j = 0; j < 4; ++j) {
            float lo, hi;
            unpack_f2(acc[i][j], lo, hi);
            outp[(ti + 16 * i) * DV_ + (tj + 16 * j)] = lo + hi;
        }
}

__global__ void l1w_reduce_kernel(const float* __restrict__ memory,
                                  float* __restrict__ out) {
    const int e = blockIdx.x * blockDim.x + threadIdx.x;  // 0..65535
    float s = 0.0f;
#pragma unroll
    for (int c = 0; c < NCHUNK_; ++c)
        s += g_l1w_scratch[(size_t)c * (H_ * DK_ * DV_) + e];
    out[e] = DECAY_ * memory[e] + s;
}

extern "C" void kernel_launch(void* const* d_in, const int* in_sizes, int n_in,
                              void* d_out, int out_size) {
    const float* memory = (const float*)d_in[0];   // (16,64,64)
    const float* keys   = (const float*)d_in[1];   // (4,4096,16,64)
    const float* values = (const float*)d_in[2];   // (4,4096,16,64)
    const float* ws     = (const float*)d_in[3];   // (4,4096)
    float* out = (float*)d_out;                    // (16,64,64)

    l1w_partial_kernel<<<NCHUNK_ * H_, 256>>>(keys, values, ws);
    l1w_reduce_kernel<<<(H_ * DK_ * DV_) / 256, 256>>>(memory, out);
}

// round 6
// speedup vs baseline: 1.2293x; 1.2293x over previous
#include <cuda_runtime.h>
#include <cstdint>

// Problem constants: B=4, S=4096, H=16, Dk=Dv=64
#define H_      16
#define DK_     64
#define DV_     64
#define HD_     1024          // floats per (b,s) row in keys/values = H*64
#define NROWS_  16384         // B*S
#define RT_     32            // rows per smem tile
#define TPB_    8             // tiles per block -> 256 rows per block
#define NCHUNK_ 64            // row-chunks per head
#define KPADF_  68            // floats per K smem row (64 + 4 pad)
#define VPAD64_ 34            // b64 words per V smem row (32 + 2 pad)
#define DECAY_  0.95f

typedef unsigned long long ull;

// Partial-sum scratch: one 64x64 tile per block (deterministic, no atomics).
__device__ float g_l1w_scratch[NCHUNK_ * H_ * DK_ * DV_];

__device__ __forceinline__ ull dup_f2(float x) {
    ull r;
    asm("mov.b64 %0, {%1, %1};" : "=l"(r) : "f"(x));
    return r;
}
__device__ __forceinline__ void ffma2(ull& d, ull a, ull b) {
    asm("fma.rn.f32x2 %0, %1, %2, %0;" : "+l"(d) : "l"(a), "l"(b));
}

__global__ __launch_bounds__(64, 5)
void l1w_partial_kernel(const float* __restrict__ keys,
                        const float* __restrict__ values,
                        const float* __restrict__ ws) {
    // Natural layouts. K: fp32 [row][col] (kk via LDS.32 broadcast).
    // V: f32x2 adjacent-col pairs [row][pair], w pre-folded (vv via LDS.64).
    __shared__ __align__(16) float sK[RT_ * KPADF_];
    __shared__ __align__(16) ull   sV[RT_ * VPAD64_];

    const int h   = blockIdx.x & (H_ - 1);
    const int c   = blockIdx.x >> 4;
    const int tid = threadIdx.x;

    // compute mapping: thread covers k-cols {ti+8i}, v-col-pairs {tj+8j}
    const int ti = tid >> 3;          // 0..7
    const int tj = tid & 7;           // 0..7
    // fill mapping: base row fr (0..7), base float4-col fc (0..7)
    const int fr = tid >> 3;
    const int fc = tid & 7;

    const int n0 = c * (RT_ * TPB_);
    const float* kbase = keys   + (size_t)h * DK_;
    const float* vbase = values + (size_t)h * DV_;

    ull acc[8][4];
#pragma unroll
    for (int i = 0; i < 8; ++i)
#pragma unroll
        for (int j = 0; j < 4; ++j) acc[i][j] = 0ull;

    float4 kst[8], vst[8];
    float  wst[4];

    // ---- prefetch tile 0 ----
#pragma unroll
    for (int s = 0; s < 8; ++s) {
        const int r  = fr + 8 * (s & 3);
        const int c4 = fc + 8 * (s >> 2);
        const size_t g = (size_t)(n0 + r) * HD_ + c4 * 4;
        kst[s] = *(const float4*)(kbase + g);
        vst[s] = *(const float4*)(vbase + g);
    }
#pragma unroll
    for (int a = 0; a < 4; ++a) wst[a] = ws[n0 + fr + 8 * a];

    for (int t = 0; t < TPB_; ++t) {
        __syncthreads();   // previous tile's compute finished
        // ---- store staged tile (w folded into V) ----
#pragma unroll
        for (int s = 0; s < 8; ++s) {
            const int r  = fr + 8 * (s & 3);
            const int c4 = fc + 8 * (s >> 2);
            *(float4*)(sK + r * KPADF_ + c4 * 4) = kst[s];
            float4 v = vst[s];
            const float w = wst[s & 3];
            v.x *= w; v.y *= w; v.z *= w; v.w *= w;
            *(float4*)((char*)sV + (size_t)(r * VPAD64_ + 2 * c4) * 8) = v;
        }
        __syncthreads();

        // ---- issue next tile's global loads (hidden under compute) ----
        if (t + 1 < TPB_) {
            const int row0 = n0 + (t + 1) * RT_;
#pragma unroll
            for (int s = 0; s < 8; ++s) {
                const int r  = fr + 8 * (s & 3);
                const int c4 = fc + 8 * (s >> 2);
                const size_t g = (size_t)(row0 + r) * HD_ + c4 * 4;
                kst[s] = *(const float4*)(kbase + g);
                vst[s] = *(const float4*)(vbase + g);
            }
#pragma unroll
            for (int a = 0; a < 4; ++a) wst[a] = ws[row0 + fr + 8 * a];
        }

        // ---- compute: 32 rows, 8x8 tile via f32x2 col-pairs ----
#pragma unroll 4
        for (int q = 0; q < RT_; ++q) {
            const float* kq = sK + q * KPADF_;
            const ull*   vq = sV + q * VPAD64_;
            ull kd[8], vv[4];
#pragma unroll
            for (int i = 0; i < 8; ++i) kd[i] = dup_f2(kq[ti + 8 * i]);
#pragma unroll
            for (int j = 0; j < 4; ++j) vv[j] = vq[tj + 8 * j];
#pragma unroll
            for (int i = 0; i < 8; ++i)
#pragma unroll
                for (int j = 0; j < 4; ++j)
                    ffma2(acc[i][j], kd[i], vv[j]);
        }
    }

    // ---- epilogue: acc pair = two adjacent output cols -> STG.64 ----
    ull* outp = (ull*)(g_l1w_scratch + ((size_t)blockIdx.x << 12));
#pragma unroll
    for (int i = 0; i < 8; ++i)
#pragma unroll
        for (int j = 0; j < 4; ++j)
            outp[(ti + 8 * i) * (DV_ / 2) + (tj + 8 * j)] = acc[i][j];
}

__global__ void l1w_reduce_kernel(const float* __restrict__ memory,
                                  float* __restrict__ out) {
    const int e = blockIdx.x * blockDim.x + threadIdx.x;  // 0..65535
    float s = 0.0f;
#pragma unroll
    for (int c = 0; c < NCHUNK_; ++c)
        s += g_l1w_scratch[(size_t)c * (H_ * DK_ * DV_) + e];
    out[e] = DECAY_ * memory[e] + s;
}

extern "C" void kernel_launch(void* const* d_in, const int* in_sizes, int n_in,
                              void* d_out, int out_size) {
    const float* memory = (const float*)d_in[0];   // (16,64,64)
    const float* keys   = (const float*)d_in[1];   // (4,4096,16,64)
    const float* values = (const float*)d_in[2];   // (4,4096,16,64)
    const float* ws     = (const float*)d_in[3];   // (4,4096)
    float* out = (float*)d_out;                    // (16,64,64)

    l1w_partial_kernel<<<NCHUNK_ * H_, 64>>>(keys, values, ws);
    l1w_reduce_kernel<<<(H_ * DK_ * DV_) / 256, 256>>>(memory, out);
}

// round 8
// speedup vs baseline: 1.9459x; 1.5830x over previous
#include <cuda_runtime.h>
#include <cuda_bf16.h>
#include <cstdint>

// Problem: B=4, S=4096, H=16, Dk=Dv=64.  out = 0.95*M + sum_rows w*k v^T per head.
#define H_      16
#define DK_     64
#define DV_     64
#define HD_     1024          // floats per (b,s) row = H*64
#define NCHUNK_ 37            // chunks/head -> grid 16*37 = 592 = 148*4 (one wave)
#define DECAY_  0.95f

// SMEM planes (u32 indices). Layout: plane[kp*72 + col], kp=row-pair 0..31, col 0..63.
// Stride 72 => fragment LDS banks (8c+r)%32 conflict-free. V bases +2 mod 4 vs K
// so the pointer-selected K/V STS instruction hits disjoint bank sets.
#define KHI_  0
#define KLO_  2304
#define VHI_  4610
#define VLO_  6914
#define SMW_  9220

__device__ float g_l1w_scratch[NCHUNK_ * H_ * DK_ * DV_];

// hi = bf16x2{lo-half=bf16(x0), hi-half=bf16(x1)}; lo = bf16x2 of residuals
__device__ __forceinline__ void split2(float x0, float x1, uint32_t& hi, uint32_t& lo) {
    asm("cvt.rn.bf16x2.f32 %0, %1, %2;" : "=r"(hi) : "f"(x1), "f"(x0));
    float h0 = __uint_as_float(hi << 16);
    float h1 = __uint_as_float(hi & 0xffff0000u);
    float l0 = x0 - h0;
    float l1 = x1 - h1;
    asm("cvt.rn.bf16x2.f32 %0, %1, %2;" : "=r"(lo) : "f"(l1), "f"(l0));
}

__device__ __forceinline__ void mma16816(float* c, const uint32_t* a,
                                         uint32_t b0, uint32_t b1) {
    asm volatile(
        "mma.sync.aligned.m16n8k16.row.col.f32.bf16.bf16.f32 "
        "{%0,%1,%2,%3}, {%4,%5,%6,%7}, {%8,%9}, {%0,%1,%2,%3};"
        : "+f"(c[0]), "+f"(c[1]), "+f"(c[2]), "+f"(c[3])
        : "r"(a[0]), "r"(a[1]), "r"(a[2]), "r"(a[3]), "r"(b0), "r"(b1));
}

__global__ __launch_bounds__(128, 4)
void l1w_hmma_kernel(const float* __restrict__ keys,
                     const float* __restrict__ values,
                     const float* __restrict__ ws) {
    __shared__ uint32_t sm[SMW_];

    const int tid  = threadIdx.x;
    const int wid  = tid >> 5;
    const int lane = tid & 31;
    const int bid  = blockIdx.x;
    const int h    = bid & 15;
    const int c    = bid >> 4;
    // 256 stages of 64 rows over 37 chunks: 34 chunks x7, 3 chunks x6
    const int nt = (c < 34) ? 7 : 6;
    const int s0 = (c < 34) ? 7 * c : 238 + 6 * (c - 34);

    const int rsel = lane >> 4;       // 0: even row / K-writer, 1: odd row / V-writer
    const int q    = lane & 15;       // float4 column group (cols 4q..4q+3)

    const float* kbase = keys   + (size_t)h * DK_;
    const float* vbase = values + (size_t)h * DV_;

    // Per-warp accumulators: C[64 m x 16 n] -> [mt][ntile][4]
    float cacc[4][2][4];
#pragma unroll
    for (int mt = 0; mt < 4; ++mt)
#pragma unroll
        for (int n2 = 0; n2 < 2; ++n2)
#pragma unroll
            for (int i = 0; i < 4; ++i) cacc[mt][n2][i] = 0.0f;

    const uint32_t baseHi = rsel ? VHI_ : KHI_;
    const uint32_t baseLo = rsel ? VLO_ : KLO_;

    for (int s = 0; s < nt; ++s) {
        const int row0 = (s0 + s) * 64;
        __syncthreads();   // previous stage's fragment LDS complete in all warps

        // ---- fill: 8 iterations, each warp stages 2 full rows (coalesced) ----
        int rowA = row0 + 2 * wid + rsel;
        float4 kc = *(const float4*)(kbase + (size_t)rowA * HD_ + 4 * q);
        float4 vc = *(const float4*)(vbase + (size_t)rowA * HD_ + 4 * q);
        float  wc = ws[rowA];

#pragma unroll
        for (int it = 0; it < 8; ++it) {
            float4 kn, vn; float wn = 0.0f;
            if (it < 7) {
                const int rowN = row0 + (it + 1) * 8 + 2 * wid + rsel;
                kn = *(const float4*)(kbase + (size_t)rowN * HD_ + 4 * q);
                vn = *(const float4*)(vbase + (size_t)rowN * HD_ + 4 * q);
                wn = ws[rowN];
            }
            // fold weight into V
            vc.x *= wc; vc.y *= wc; vc.z *= wc; vc.w *= wc;

            // exchange: rsel0 sends V (partner wants V), rsel1 sends K
            float me[4], rc[4];
            const float* kf = &kc.x; const float* vf = &vc.x;
#pragma unroll
            for (int j = 0; j < 4; ++j) {
                me[j] = rsel ? vf[j] : kf[j];                 // matrix I write
                float src = rsel ? kf[j] : vf[j];             // matrix partner writes
                rc[j] = __shfl_xor_sync(0xffffffffu, src, 16);
            }

            const uint32_t kp = (uint32_t)(it * 4 + wid);
            const uint32_t wbase = kp * 72u + 4u * q;
#pragma unroll
            for (int j = 0; j < 4; ++j) {
                // even row value / odd row value for my matrix
                const float e = rsel ? rc[j] : me[j];
                const float o = rsel ? me[j] : rc[j];
                uint32_t hi, lo;
                split2(e, o, hi, lo);
                sm[baseHi + wbase + j] = hi;
                sm[baseLo + wbase + j] = lo;
            }
            kc = kn; vc = vn; wc = wn;
        }
        __syncthreads();

        // ---- compute: 4 k-steps x (4 m-tiles x 2 n-tiles) x 3 products ----
        const int r2 = lane >> 2;
        const int c2 = lane & 3;
        const int nb = wid * 16;
#pragma unroll
        for (int st = 0; st < 4; ++st) {
            const uint32_t krow = (uint32_t)((8 * st + c2) * 72);
            uint32_t aH[4][4], aL[4][4], bH[2][2], bL[2][2];
#pragma unroll
            for (int mt = 0; mt < 4; ++mt) {
                const uint32_t cc = (uint32_t)(16 * mt + r2);
                aH[mt][0] = sm[KHI_ + krow + cc];
                aH[mt][1] = sm[KHI_ + krow + cc + 8];
                aH[mt][2] = sm[KHI_ + krow + 288 + cc];
                aH[mt][3] = sm[KHI_ + krow + 288 + cc + 8];
                aL[mt][0] = sm[KLO_ + krow + cc];
                aL[mt][1] = sm[KLO_ + krow + cc + 8];
                aL[mt][2] = sm[KLO_ + krow + 288 + cc];
                aL[mt][3] = sm[KLO_ + krow + 288 + cc + 8];
            }
#pragma unroll
            for (int n2 = 0; n2 < 2; ++n2) {
                const uint32_t nn = (uint32_t)(nb + 8 * n2 + r2);
                bH[n2][0] = sm[VHI_ + krow + nn];
                bH[n2][1] = sm[VHI_ + krow + 288 + nn];
                bL[n2][0] = sm[VLO_ + krow + nn];
                bL[n2][1] = sm[VLO_ + krow + 288 + nn];
            }
#pragma unroll
            for (int mt = 0; mt < 4; ++mt)
#pragma unroll
                for (int n2 = 0; n2 < 2; ++n2) {
                    mma16816(cacc[mt][n2], aH[mt], bH[n2][0], bH[n2][1]);
                    mma16816(cacc[mt][n2], aH[mt], bL[n2][0], bL[n2][1]);
                    mma16816(cacc[mt][n2], aL[mt], bH[n2][0], bH[n2][1]);
                }
        }
    }

    // ---- epilogue: write per-warp 64x16 partial tile ----
    float* outp = g_l1w_scratch + ((size_t)c << 16) + ((size_t)h << 12);
#pragma unroll
    for (int mt = 0; mt < 4; ++mt)
#pragma unroll
        for (int n2 = 0; n2 < 2; ++n2) {
            const int row = 16 * mt + (lane >> 2);
            const int col = wid * 16 + 8 * n2 + 2 * (lane & 3);
            float2 lo = make_float2(cacc[mt][n2][0], cacc[mt][n2][1]);
            float2 hi = make_float2(cacc[mt][n2][2], cacc[mt][n2][3]);
            *(float2*)(outp + (size_t)row * DV_ + col) = lo;
            *(float2*)(outp + (size_t)(row + 8) * DV_ + col) = hi;
        }
}

__global__ void l1w_reduce_kernel(const float* __restrict__ memory,
                                  float* __restrict__ out) {
    const int e4 = blockIdx.x * blockDim.x + threadIdx.x;   // 0..16383 (float4)
    const float4* sc4 = (const float4*)g_l1w_scratch;
    float4 s = make_float4(0.f, 0.f, 0.f, 0.f);
#pragma unroll
    for (int c = 0; c < NCHUNK_; ++c) {
        float4 t = sc4[(size_t)c * 16384 + e4];
        s.x += t.x; s.y += t.y; s.z += t.z; s.w += t.w;
    }
    float4 m = ((const float4*)memory)[e4];
    float4 o;
    o.x = DECAY_ * m.x + s.x;
    o.y = DECAY_ * m.y + s.y;
    o.z = DECAY_ * m.z + s.z;
    o.w = DECAY_ * m.w + s.w;
    ((float4*)out)[e4] = o;
}

extern "C" void kernel_launch(void* const* d_in, const int* in_sizes, int n_in,
                              void* d_out, int out_size) {
    const float* memory = (const float*)d_in[0];   // (16,64,64)
    const float* keys   = (const float*)d_in[1];   // (4,4096,16,64)
    const float* values = (const float*)d_in[2];   // (4,4096,16,64)
    const float* ws     = (const float*)d_in[3];   // (4,4096)
    float* out = (float*)d_out;                    // (16,64,64)

    l1w_hmma_kernel<<<NCHUNK_ * H_, 128>>>(keys, values, ws);
    l1w_reduce_kernel<<<128, 128>>>(memory, out);
}